// round 2
// baseline (speedup 1.0000x reference)
#include <cuda_runtime.h>
#include <math.h>

#define NN 2048
#define DD 128
#define FF 8
#define BM 32
#define BN 128
#define KC 32
#define TM 4
#define TN 4
#define DSPITCH 132   // pitch for ds tile: 132 % 32 = 4 -> 4-way store conflict only; 132*4 % 16 == 0 for LDS.128

// Scratch (device globals: no runtime allocation allowed)
__device__ float  g_qn[FF * NN * DD];   // normalized query  [F][N][D]
__device__ float  g_dn[FF * NN * DD];   // normalized doc    [F][N][D]
__device__ float  g_dS[FF * NN];        // sim diagonal
__device__ float  g_dL[FF * NN];        // label diagonal
__device__ double g_loss;
__device__ int    g_count;

__global__ void k_init() {
    g_loss = 0.0;
    g_count = 0;
}

// out_matrix: [2, N, D, F] -> normalized, transposed to [F][N][D]
__global__ void k_norm(const float* __restrict__ in0) {
    int s = blockIdx.y;
    int n = blockIdx.x;
    int w = threadIdx.x >> 5;      // warp id = f
    int lane = threadIdx.x & 31;
    const float* base = in0 + ((size_t)(s * NN + n)) * DD * FF;
    float v[4];
    float ssq = 0.f;
#pragma unroll
    for (int k = 0; k < 4; k++) {
        int d = lane + 32 * k;
        v[k] = base[d * FF + w];
        ssq += v[k] * v[k];
    }
#pragma unroll
    for (int off = 16; off; off >>= 1)
        ssq += __shfl_xor_sync(0xffffffffu, ssq, off);
    float rn = 1.0f / sqrtf(ssq);
    float* out = (s == 0 ? g_qn : g_dn) + ((size_t)(w * NN + n)) * DD;
#pragma unroll
    for (int k = 0; k < 4; k++)
        out[lane + 32 * k] = v[k] * rn;
}

// diag_s[f][n] = qn[f][n] . dn[f][n] ; diag_l[f][n] = label[f][n][n]
__global__ void k_diag(const float* __restrict__ label) {
    int gw = blockIdx.x * 8 + (threadIdx.x >> 5);   // global warp id = f*N + n
    int lane = threadIdx.x & 31;
    int n = gw & (NN - 1);
    const float* q = g_qn + ((size_t)gw) * DD;
    const float* d = g_dn + ((size_t)gw) * DD;
    float s = 0.f;
#pragma unroll
    for (int k = 0; k < 4; k++) {
        int dd = lane + 32 * k;
        s += q[dd] * d[dd];
    }
#pragma unroll
    for (int off = 16; off; off >>= 1)
        s += __shfl_xor_sync(0xffffffffu, s, off);
    if (lane == 0) {
        g_dS[gw] = s;
        g_dL[gw] = label[((size_t)gw) * NN + n];
    }
}

// Fused SGEMM (sim tile) + hinge loss + row argmax (sim & label)
__global__ void __launch_bounds__(256) k_main(const float* __restrict__ label,
                                              const float* __restrict__ pmargin) {
    __shared__ __align__(16) float qs[DD * BM];        // [k][row], full K resident
    __shared__ __align__(16) float ds[KC * DSPITCH];   // [kk][col]

    const int f = blockIdx.y;
    const int i0 = blockIdx.x * BM;
    const int tid = threadIdx.x;
    const int tx = tid & 31;
    const int ty = tid >> 5;
    const float margin = *pmargin;

    // load q strip: qs[k][r] = qn[f][i0+r][k]  (coalesced global read)
    {
        const float* qb = g_qn + ((size_t)(f * NN) + i0) * DD;
        for (int idx = tid; idx < BM * DD; idx += 256) {
            int r = idx >> 7;      // / 128
            int k = idx & 127;
            qs[k * BM + r] = qb[idx];
        }
    }

    const int r0 = ty * TM;
    const int c0 = tx * TN;

    float dSr[TM], dLr[TM];
#pragma unroll
    for (int rr = 0; rr < TM; rr++) {
        dSr[rr] = g_dS[f * NN + i0 + r0 + rr];
        dLr[rr] = g_dL[f * NN + i0 + r0 + rr];
    }

    float simmax[TM], labmax[TM];
    int simidx[TM], labidx[TM];
#pragma unroll
    for (int rr = 0; rr < TM; rr++) {
        simmax[rr] = -INFINITY; labmax[rr] = -INFINITY;
        simidx[rr] = 0;         labidx[rr] = 0;
    }
    float lloss = 0.f;

    const float* db = g_dn + ((size_t)f * NN) * DD;
    const float* lb = label + (((size_t)f * NN) + i0) * NN;

    for (int j0 = 0; j0 < NN; j0 += BN) {
        float acc[TM * TN];
#pragma unroll
        for (int u = 0; u < TM * TN; u++) acc[u] = 0.f;

        for (int kc = 0; kc < DD; kc += KC) {
            __syncthreads();
            // ds[kk][c] = dn[f][j0+c][kc+kk]  (coalesced 128B global reads)
            for (int idx = tid; idx < BN * KC; idx += 256) {
                int c = idx >> 5;       // / KC
                int kk = idx & 31;      // % KC
                ds[kk * DSPITCH + c] = db[(size_t)(j0 + c) * DD + kc + kk];
            }
            __syncthreads();
#pragma unroll
            for (int kk = 0; kk < KC; kk++) {
                float4 a4 = *(const float4*)&qs[(kc + kk) * BM + r0];
                float4 b4 = *(const float4*)&ds[kk * DSPITCH + c0];
                float a[4] = {a4.x, a4.y, a4.z, a4.w};
                float b[4] = {b4.x, b4.y, b4.z, b4.w};
#pragma unroll
                for (int rr = 0; rr < TM; rr++)
#pragma unroll
                    for (int cc = 0; cc < TN; cc++)
                        acc[rr * TN + cc] += a[rr] * b[cc];
            }
        }

        // epilogue for this j-tile
#pragma unroll
        for (int rr = 0; rr < TM; rr++) {
            const int i = i0 + r0 + rr;
            float4 l4 = *(const float4*)&lb[(size_t)(r0 + rr) * NN + j0 + c0];
            float lv[4] = {l4.x, l4.y, l4.z, l4.w};
#pragma unroll
            for (int cc = 0; cc < TN; cc++) {
                int j = j0 + c0 + cc;
                float s = acc[rr * TN + cc];
                float l = lv[cc];
                if (s > simmax[rr]) { simmax[rr] = s; simidx[rr] = j; }
                if (l > labmax[rr]) { labmax[rr] = l; labidx[rr] = j; }
                float t = margin - (dSr[rr] - s) * (dLr[rr] - l);
                lloss += (i == j) ? 0.f : fmaxf(t, 0.f);
            }
        }
    }

    // ---- loss block reduction (reuse qs) ----
    __syncthreads();
    qs[tid] = lloss;
    __syncthreads();
    for (int sft = 128; sft; sft >>= 1) {
        if (tid < sft) qs[tid] += qs[tid + sft];
        __syncthreads();
    }
    if (tid == 0) atomicAdd(&g_loss, (double)qs[0]);

    // ---- argmax warp reduction (warp = fixed ty; lanes tx hold column candidates) ----
    int cnt = 0;
#pragma unroll
    for (int rr = 0; rr < TM; rr++) {
        float v = simmax[rr]; int ix = simidx[rr];
#pragma unroll
        for (int off = 16; off; off >>= 1) {
            float v2 = __shfl_xor_sync(0xffffffffu, v, off);
            int i2 = __shfl_xor_sync(0xffffffffu, ix, off);
            if (v2 > v || (v2 == v && i2 < ix)) { v = v2; ix = i2; }
        }
        float w = labmax[rr]; int jx = labidx[rr];
#pragma unroll
        for (int off = 16; off; off >>= 1) {
            float w2 = __shfl_xor_sync(0xffffffffu, w, off);
            int j2 = __shfl_xor_sync(0xffffffffu, jx, off);
            if (w2 > w || (w2 == w && j2 < jx)) { w = w2; jx = j2; }
        }
        if (tx == 0 && ix == jx) cnt++;
    }
    if (tx == 0 && cnt) atomicAdd(&g_count, cnt);
}

__global__ void k_final(float* out, int nout) {
    if (threadIdx.x == 0) {
        if (nout > 0) out[0] = (float)g_loss;
        if (nout > 1) out[1] = (float)g_count;
    }
}

extern "C" void kernel_launch(void* const* d_in, const int* in_sizes, int n_in,
                              void* d_out, int out_size) {
    const float* out_matrix = (const float*)d_in[0];   // [2, N, D, F] f32
    const float* label      = (const float*)d_in[1];   // [F, N, N] f32
    const float* margin     = (const float*)d_in[2];   // scalar f32
    float* out = (float*)d_out;

    k_init<<<1, 1>>>();
    dim3 gn(NN, 2);
    k_norm<<<gn, 256>>>(out_matrix);
    k_diag<<<FF * NN / 8, 256>>>(label);
    dim3 gm(NN / BM, FF);
    k_main<<<gm, 256>>>(label, margin);
    k_final<<<1, 32>>>(out, out_size);
}

// round 4
// speedup vs baseline: 2.6928x; 2.6928x over previous
#include <cuda_runtime.h>
#include <cuda_bf16.h>
#include <math.h>
#include <stdint.h>

#define NN 2048
#define DD 128
#define FF 8
#define TILE 128
#define NTILE (NN / TILE)
#define THREADS 256

__device__ __nv_bfloat16 g_qh[FF * NN * DD];
__device__ __nv_bfloat16 g_ql[FF * NN * DD];
__device__ __nv_bfloat16 g_dh[FF * NN * DD];
__device__ __nv_bfloat16 g_dl[FF * NN * DD];
__device__ float  g_dS[FF * NN];
__device__ float  g_dL[FF * NN];
__device__ double g_loss;
__device__ int    g_count;

__device__ __forceinline__ uint32_t smem_u32(const void* p) {
    uint32_t a;
    asm("{ .reg .u64 t; cvta.to.shared.u64 t, %1; cvt.u32.u64 %0, t; }" : "=r"(a) : "l"(p));
    return a;
}
__device__ __forceinline__ void cpa16(uint32_t dst, const void* src) {
    asm volatile("cp.async.cg.shared.global [%0], [%1], 16;" :: "r"(dst), "l"(src) : "memory");
}
#define CP_COMMIT() asm volatile("cp.async.commit_group;" ::: "memory")
#define CP_WAIT0()  asm volatile("cp.async.wait_group 0;" ::: "memory")

#define LDSM4(r, addr) \
    asm volatile("ldmatrix.sync.aligned.m8n8.x4.shared.b16 {%0,%1,%2,%3}, [%4];" \
                 : "=r"((r)[0]), "=r"((r)[1]), "=r"((r)[2]), "=r"((r)[3]) : "r"(addr))
#define LDSM2(r, addr) \
    asm volatile("ldmatrix.sync.aligned.m8n8.x2.shared.b16 {%0,%1}, [%2];" \
                 : "=r"((r)[0]), "=r"((r)[1]) : "r"(addr))

__device__ __forceinline__ void mma_bf16(float* c, const uint32_t* a, const uint32_t* b) {
    asm volatile(
        "mma.sync.aligned.m16n8k16.row.col.f32.bf16.bf16.f32 "
        "{%0,%1,%2,%3}, {%4,%5,%6,%7}, {%8,%9}, {%0,%1,%2,%3};"
        : "+f"(c[0]), "+f"(c[1]), "+f"(c[2]), "+f"(c[3])
        : "r"(a[0]), "r"(a[1]), "r"(a[2]), "r"(a[3]), "r"(b[0]), "r"(b[1]));
}

__device__ __forceinline__ uint32_t swz(int row, int chunk) {
    return (uint32_t)(row * 256 + ((chunk ^ (row & 7)) << 4));
}

#define SM_AH 0
#define SM_AL 32768
#define SM_B0 65536
#define SM_TOTAL (65536 + 2 * 65536)

__global__ void k_init() { g_loss = 0.0; g_count = 0; }

__global__ void k_norm(const float* __restrict__ in0) {
    int s = blockIdx.y, n = blockIdx.x;
    int f = threadIdx.x >> 5, lane = threadIdx.x & 31;
    const float* base = in0 + ((size_t)(s * NN + n)) * DD * FF;
    float v[4], ssq = 0.f;
#pragma unroll
    for (int k = 0; k < 4; k++) {
        v[k] = base[(lane + 32 * k) * FF + f];
        ssq += v[k] * v[k];
    }
#pragma unroll
    for (int off = 16; off; off >>= 1) ssq += __shfl_xor_sync(0xffffffffu, ssq, off);
    float rn = 1.0f / sqrtf(ssq);
    __nv_bfloat16* oh = (s == 0 ? g_qh : g_dh) + ((size_t)(f * NN + n)) * DD;
    __nv_bfloat16* ol = (s == 0 ? g_ql : g_dl) + ((size_t)(f * NN + n)) * DD;
#pragma unroll
    for (int k = 0; k < 4; k++) {
        float x = v[k] * rn;
        __nv_bfloat16 h = __float2bfloat16(x);
        oh[lane + 32 * k] = h;
        ol[lane + 32 * k] = __float2bfloat16(x - __bfloat162float(h));
    }
}

__global__ void k_diag(const float* __restrict__ label) {
    int gw = blockIdx.x * 8 + (threadIdx.x >> 5);
    int lane = threadIdx.x & 31;
    int n = gw & (NN - 1);
    const __nv_bfloat16* qh = g_qh + (size_t)gw * DD;
    const __nv_bfloat16* ql = g_ql + (size_t)gw * DD;
    const __nv_bfloat16* dh = g_dh + (size_t)gw * DD;
    const __nv_bfloat16* dl = g_dl + (size_t)gw * DD;
    float s = 0.f;
#pragma unroll
    for (int k = 0; k < 4; k++) {
        int d = lane + 32 * k;
        float a = __bfloat162float(qh[d]), al = __bfloat162float(ql[d]);
        float b = __bfloat162float(dh[d]), bl = __bfloat162float(dl[d]);
        s += a * b + a * bl + al * b;
    }
#pragma unroll
    for (int off = 16; off; off >>= 1) s += __shfl_xor_sync(0xffffffffu, s, off);
    if (lane == 0) {
        g_dS[gw] = s;
        g_dL[gw] = label[(size_t)gw * NN + n];
    }
}

__device__ __forceinline__ void load_tile_async(uint32_t smbase, const __nv_bfloat16* src, int tid) {
#pragma unroll
    for (int it = 0; it < 2048 / THREADS; it++) {
        int idx = tid + it * THREADS;
        int row = idx >> 4, c = idx & 15;
        cpa16(smbase + swz(row, c), src + row * DD + c * 8);
    }
}

__global__ void __launch_bounds__(THREADS, 1) k_gemm(const float* __restrict__ label,
                                                     const float* __restrict__ pmargin) {
    extern __shared__ __align__(1024) char sm[];
    const uint32_t smb = smem_u32(sm);
    const int tid = threadIdx.x;
    const int w = tid >> 5, lane = tid & 31;
    const int g = lane >> 2, t4 = lane & 3;
    const int f = blockIdx.y;
    const int i0 = blockIdx.x * TILE;
    const float margin = *pmargin;
    const size_t fb = (size_t)f * NN;

    const int rA = i0 + 16 * w + g;
    const int rB = rA + 8;

    load_tile_async(smb + SM_AH, g_qh + (fb + i0) * DD, tid);
    load_tile_async(smb + SM_AL, g_ql + (fb + i0) * DD, tid);
    load_tile_async(smb + SM_B0,         g_dh + fb * DD, tid);
    load_tile_async(smb + SM_B0 + 32768, g_dl + fb * DD, tid);
    CP_COMMIT();

    const float dSA = g_dS[fb + rA], dLA = g_dL[fb + rA];
    const float dSB = g_dS[fb + rB], dLB = g_dL[fb + rB];
    const float* lrowA = label + (fb + rA) * NN;
    const float* lrowB = label + (fb + rB) * NN;

    float smA = -INFINITY, lmA = -INFINITY, smB = -INFINITY, lmB = -INFINITY;
    int siA = 0, liA = 0, siB = 0, liB = 0;
    float loss = 0.f;

    const int arow = 16 * w + (lane & 15);
    const int ahalf = lane >> 4;             // 0/1: which k-half chunk
    const int brow = lane & 7;
    const int bhalf = (lane >> 3) & 1;

#pragma unroll 1
    for (int t = 0; t < NTILE; t++) {
        CP_WAIT0();
        __syncthreads();
        if (t + 1 < NTILE) {
            uint32_t nb = smb + SM_B0 + (uint32_t)((t + 1) & 1) * 65536;
            load_tile_async(nb,         g_dh + (fb + (size_t)(t + 1) * TILE) * DD, tid);
            load_tile_async(nb + 32768, g_dl + (fb + (size_t)(t + 1) * TILE) * DD, tid);
            CP_COMMIT();
        }
        const uint32_t bb = smb + SM_B0 + (uint32_t)(t & 1) * 65536;

        float acc[16][4];
#pragma unroll
        for (int nt = 0; nt < 16; nt++)
#pragma unroll
            for (int u = 0; u < 4; u++) acc[nt][u] = 0.f;

#pragma unroll
        for (int ks = 0; ks < 8; ks++) {
            uint32_t ah[4], al[4];
            uint32_t aoff = swz(arow, 2 * ks + ahalf);
            LDSM4(ah, smb + SM_AH + aoff);
            LDSM4(al, smb + SM_AL + aoff);
#pragma unroll
            for (int nt = 0; nt < 16; nt++) {
                uint32_t bh[2], bl[2];
                uint32_t boff = swz(8 * nt + brow, 2 * ks + bhalf);
                LDSM2(bh, bb + boff);
                LDSM2(bl, bb + 32768 + boff);
                mma_bf16(acc[nt], ah, bh);
                mma_bf16(acc[nt], ah, bl);
                mma_bf16(acc[nt], al, bh);
            }
        }

        const int j0 = t * TILE;
#pragma unroll
        for (int nt = 0; nt < 16; nt++) {
            const int j = j0 + nt * 8 + t4 * 2;
            float2 lA = *(const float2*)(lrowA + j);
            float2 lB = *(const float2*)(lrowB + j);

            float s0 = acc[nt][0], s1 = acc[nt][1], s2 = acc[nt][2], s3 = acc[nt][3];
            if (s0 > smA) { smA = s0; siA = j; }
            if (s1 > smA) { smA = s1; siA = j + 1; }
            if (s2 > smB) { smB = s2; siB = j; }
            if (s3 > smB) { smB = s3; siB = j + 1; }
            if (lA.x > lmA) { lmA = lA.x; liA = j; }
            if (lA.y > lmA) { lmA = lA.y; liA = j + 1; }
            if (lB.x > lmB) { lmB = lB.x; liB = j; }
            if (lB.y > lmB) { lmB = lB.y; liB = j + 1; }

            float h0 = margin - (dSA - s0) * (dLA - lA.x);
            float h1 = margin - (dSA - s1) * (dLA - lA.y);
            float h2 = margin - (dSB - s2) * (dLB - lB.x);
            float h3 = margin - (dSB - s3) * (dLB - lB.y);
            if (j     != rA) loss += fmaxf(h0, 0.f);
            if (j + 1 != rA) loss += fmaxf(h1, 0.f);
            if (j     != rB) loss += fmaxf(h2, 0.f);
            if (j + 1 != rB) loss += fmaxf(h3, 0.f);
        }
    }

#pragma unroll
    for (int off = 16; off; off >>= 1) loss += __shfl_xor_sync(0xffffffffu, loss, off);
    if (lane == 0) atomicAdd(&g_loss, (double)loss);

#pragma unroll
    for (int o = 1; o < 4; o <<= 1) {
        float v; int ix;
        v = __shfl_xor_sync(0xffffffffu, smA, o); ix = __shfl_xor_sync(0xffffffffu, siA, o);
        if (v > smA || (v == smA && ix < siA)) { smA = v; siA = ix; }
        v = __shfl_xor_sync(0xffffffffu, lmA, o); ix = __shfl_xor_sync(0xffffffffu, liA, o);
        if (v > lmA || (v == lmA && ix < liA)) { lmA = v; liA = ix; }
        v = __shfl_xor_sync(0xffffffffu, smB, o); ix = __shfl_xor_sync(0xffffffffu, siB, o);
        if (v > smB || (v == smB && ix < siB)) { smB = v; siB = ix; }
        v = __shfl_xor_sync(0xffffffffu, lmB, o); ix = __shfl_xor_sync(0xffffffffu, liB, o);
        if (v > lmB || (v == lmB && ix < liB)) { lmB = v; liB = ix; }
    }
    int c = (t4 == 0) ? ((siA == liA) + (siB == liB)) : 0;
    c = __reduce_add_sync(0xffffffffu, c);
    if (lane == 0 && c) atomicAdd(&g_count, c);
}

__global__ void k_final(float* out, int nout) {
    if (threadIdx.x == 0) {
        if (nout > 0) out[0] = (float)g_loss;
        if (nout > 1) out[1] = (float)g_count;
    }
}

extern "C" void kernel_launch(void* const* d_in, const int* in_sizes, int n_in,
                              void* d_out, int out_size) {
    const float* out_matrix = (const float*)d_in[0];
    const float* label      = (const float*)d_in[1];
    const float* margin     = (const float*)d_in[2];
    float* out = (float*)d_out;

    cudaFuncSetAttribute(k_gemm, cudaFuncAttributeMaxDynamicSharedMemorySize, SM_TOTAL);

    k_init<<<1, 1>>>();
    dim3 gn(NN, 2);
    k_norm<<<gn, 256>>>(out_matrix);
    k_diag<<<FF * NN / 8, 256>>>(label);
    dim3 gm(NTILE, FF);
    k_gemm<<<gm, THREADS, SM_TOTAL>>>(label, margin);
    k_final<<<1, 32>>>(out, out_size);
}

// round 5
// speedup vs baseline: 3.8069x; 1.4138x over previous
#include <cuda_runtime.h>
#include <cuda_bf16.h>
#include <math.h>
#include <stdint.h>

#define NN 2048
#define DD 128
#define FF 8
#define TILE 128
#define NTILE (NN / TILE)
#define THREADS 512

__device__ __nv_bfloat16 g_qh[FF * NN * DD];
__device__ __nv_bfloat16 g_ql[FF * NN * DD];
__device__ __nv_bfloat16 g_dh[FF * NN * DD];
__device__ __nv_bfloat16 g_dl[FF * NN * DD];
__device__ float  g_dS[FF * NN];
__device__ float  g_dL[FF * NN];
__device__ double g_loss;
__device__ int    g_count;

__device__ __forceinline__ uint32_t smem_u32(const void* p) {
    uint32_t a;
    asm("{ .reg .u64 t; cvta.to.shared.u64 t, %1; cvt.u32.u64 %0, t; }" : "=r"(a) : "l"(p));
    return a;
}
__device__ __forceinline__ void cpa16(uint32_t dst, const void* src) {
    asm volatile("cp.async.cg.shared.global [%0], [%1], 16;" :: "r"(dst), "l"(src) : "memory");
}
#define CP_COMMIT() asm volatile("cp.async.commit_group;" ::: "memory")
#define CP_WAIT0()  asm volatile("cp.async.wait_group 0;" ::: "memory")

#define LDSM4(r, addr) \
    asm volatile("ldmatrix.sync.aligned.m8n8.x4.shared.b16 {%0,%1,%2,%3}, [%4];" \
                 : "=r"((r)[0]), "=r"((r)[1]), "=r"((r)[2]), "=r"((r)[3]) : "r"(addr))
#define LDSM2(r, addr) \
    asm volatile("ldmatrix.sync.aligned.m8n8.x2.shared.b16 {%0,%1}, [%2];" \
                 : "=r"((r)[0]), "=r"((r)[1]) : "r"(addr))

__device__ __forceinline__ void mma_bf16(float* c, const uint32_t* a, const uint32_t* b) {
    asm volatile(
        "mma.sync.aligned.m16n8k16.row.col.f32.bf16.bf16.f32 "
        "{%0,%1,%2,%3}, {%4,%5,%6,%7}, {%8,%9}, {%0,%1,%2,%3};"
        : "+f"(c[0]), "+f"(c[1]), "+f"(c[2]), "+f"(c[3])
        : "r"(a[0]), "r"(a[1]), "r"(a[2]), "r"(a[3]), "r"(b[0]), "r"(b[1]));
}

__device__ __forceinline__ uint32_t swz(int row, int chunk) {
    return (uint32_t)(row * 256 + ((chunk ^ (row & 7)) << 4));
}

// SMEM: A_h 32K | A_l 32K | B0 (h 32K | l 32K) | B1 (h | l)  = 192 KB
#define SM_AH 0
#define SM_AL 32768
#define SM_B0 65536
#define SM_TOTAL (65536 + 2 * 65536)

// ---------------- prep kernels ----------------
// out_matrix [2,N,D,F]; coalesced smem-staged transpose + normalize -> bf16 hi/lo
__global__ void k_norm(const float* __restrict__ in0) {
    __shared__ float sd[DD * FF];   // 1024 floats
    int s = blockIdx.y, n = blockIdx.x;
    int tid = threadIdx.x;
    if (s == 0 && n == 0 && tid == 0) { g_loss = 0.0; g_count = 0; }  // fused init
    int f = tid >> 5, lane = tid & 31;
    const float4* base = (const float4*)(in0 + ((size_t)(s * NN + n)) * DD * FF);
    *(float4*)&sd[tid * 4] = base[tid];
    __syncthreads();
    float v[4], ssq = 0.f;
#pragma unroll
    for (int k = 0; k < 4; k++) {
        v[k] = sd[(lane + 32 * k) * FF + f];
        ssq += v[k] * v[k];
    }
#pragma unroll
    for (int off = 16; off; off >>= 1) ssq += __shfl_xor_sync(0xffffffffu, ssq, off);
    float rn = 1.0f / sqrtf(ssq);
    __nv_bfloat16* oh = (s == 0 ? g_qh : g_dh) + ((size_t)(f * NN + n)) * DD;
    __nv_bfloat16* ol = (s == 0 ? g_ql : g_dl) + ((size_t)(f * NN + n)) * DD;
#pragma unroll
    for (int k = 0; k < 4; k++) {
        float x = v[k] * rn;
        __nv_bfloat16 h = __float2bfloat16(x);
        oh[lane + 32 * k] = h;
        ol[lane + 32 * k] = __float2bfloat16(x - __bfloat162float(h));
    }
}

__global__ void k_diag(const float* __restrict__ label) {
    int gw = blockIdx.x * 8 + (threadIdx.x >> 5);   // f*NN + n
    int lane = threadIdx.x & 31;
    int n = gw & (NN - 1);
    const __nv_bfloat16* qh = g_qh + (size_t)gw * DD;
    const __nv_bfloat16* ql = g_ql + (size_t)gw * DD;
    const __nv_bfloat16* dh = g_dh + (size_t)gw * DD;
    const __nv_bfloat16* dl = g_dl + (size_t)gw * DD;
    float s = 0.f;
#pragma unroll
    for (int k = 0; k < 4; k++) {
        int d = lane + 32 * k;
        float a = __bfloat162float(qh[d]), al = __bfloat162float(ql[d]);
        float b = __bfloat162float(dh[d]), bl = __bfloat162float(dl[d]);
        s += a * b + a * bl + al * b;
    }
#pragma unroll
    for (int off = 16; off; off >>= 1) s += __shfl_xor_sync(0xffffffffu, s, off);
    if (lane == 0) {
        g_dS[gw] = s;
        g_dL[gw] = label[(size_t)gw * NN + n];
    }
}

__device__ __forceinline__ void load_tile_async(uint32_t smbase, const __nv_bfloat16* src, int tid) {
#pragma unroll
    for (int it = 0; it < 2048 / THREADS; it++) {
        int idx = tid + it * THREADS;
        int row = idx >> 4, c = idx & 15;
        cpa16(smbase + swz(row, c), src + row * DD + c * 8);
    }
}

// ---------------- main fused kernel ----------------
__global__ void __launch_bounds__(THREADS, 1) k_gemm(const float* __restrict__ label,
                                                     const float* __restrict__ pmargin) {
    extern __shared__ __align__(1024) char sm[];
    const uint32_t smb = smem_u32(sm);
    const int tid = threadIdx.x;
    const int w = tid >> 5, lane = tid & 31;
    const int g = lane >> 2, t4 = lane & 3;
    const int rowgrp = w >> 2, colgrp = w & 3;
    const int f = blockIdx.y;
    const int i0 = blockIdx.x * TILE;
    const float margin = *pmargin;
    const size_t fb = (size_t)f * NN;

    load_tile_async(smb + SM_AH, g_qh + (fb + i0) * DD, tid);
    load_tile_async(smb + SM_AL, g_ql + (fb + i0) * DD, tid);
    load_tile_async(smb + SM_B0,         g_dh + fb * DD, tid);
    load_tile_async(smb + SM_B0 + 32768, g_dl + fb * DD, tid);
    CP_COMMIT();

    // thread's 4 rows: local = rowgrp*32 + mt*16 + g + h*8
    int rloc[4];
    float dS[4], dL[4];
    const float* lrow[4];
#pragma unroll
    for (int mt = 0; mt < 2; mt++)
#pragma unroll
        for (int h = 0; h < 2; h++) {
            int k = mt * 2 + h;
            rloc[k] = rowgrp * 32 + mt * 16 + g + h * 8;
            int rg = i0 + rloc[k];
            dS[k] = g_dS[fb + rg];
            dL[k] = g_dL[fb + rg];
            lrow[k] = label + (fb + rg) * NN;
        }

    float smax[4], lmax[4];
    int sidx[4], lidx[4];
#pragma unroll
    for (int k = 0; k < 4; k++) {
        smax[k] = -INFINITY; lmax[k] = -INFINITY; sidx[k] = 0; lidx[k] = 0;
    }
    float loss = 0.f;

    const int arow0 = rowgrp * 32 + (lane & 15);
    const int ahalf = lane >> 4;
    const int brow = lane & 7;
    const int bhalf = (lane >> 3) & 1;

#pragma unroll 1
    for (int t = 0; t < NTILE; t++) {
        CP_WAIT0();
        __syncthreads();
        if (t + 1 < NTILE) {
            uint32_t nb = smb + SM_B0 + (uint32_t)((t + 1) & 1) * 65536;
            load_tile_async(nb,         g_dh + (fb + (size_t)(t + 1) * TILE) * DD, tid);
            load_tile_async(nb + 32768, g_dl + (fb + (size_t)(t + 1) * TILE) * DD, tid);
            CP_COMMIT();
        }
        const uint32_t bb = smb + SM_B0 + (uint32_t)(t & 1) * 65536;

        float acc[2][4][4];
#pragma unroll
        for (int mt = 0; mt < 2; mt++)
#pragma unroll
            for (int nt = 0; nt < 4; nt++)
#pragma unroll
                for (int u = 0; u < 4; u++) acc[mt][nt][u] = 0.f;

#pragma unroll
        for (int ks = 0; ks < 8; ks++) {
            uint32_t ah0[4], al0[4], ah1[4], al1[4];
            uint32_t aoff0 = swz(arow0,      2 * ks + ahalf);
            uint32_t aoff1 = swz(arow0 + 16, 2 * ks + ahalf);
            LDSM4(ah0, smb + SM_AH + aoff0);
            LDSM4(ah1, smb + SM_AH + aoff1);
            LDSM4(al0, smb + SM_AL + aoff0);
            LDSM4(al1, smb + SM_AL + aoff1);
#pragma unroll
            for (int nt = 0; nt < 4; nt++) {
                uint32_t bh[2], bl[2];
                int ntg = colgrp * 4 + nt;
                uint32_t boff = swz(8 * ntg + brow, 2 * ks + bhalf);
                LDSM2(bh, bb + boff);
                LDSM2(bl, bb + 32768 + boff);
                mma_bf16(acc[0][nt], ah0, bh);
                mma_bf16(acc[1][nt], ah1, bh);
                mma_bf16(acc[0][nt], ah0, bl);
                mma_bf16(acc[1][nt], ah1, bl);
                mma_bf16(acc[0][nt], al0, bh);
                mma_bf16(acc[1][nt], al1, bh);
            }
        }

        // epilogue
        const int j0 = t * TILE;
#pragma unroll
        for (int mt = 0; mt < 2; mt++)
#pragma unroll
            for (int nt = 0; nt < 4; nt++) {
                const int j = j0 + (colgrp * 4 + nt) * 8 + t4 * 2;
#pragma unroll
                for (int h = 0; h < 2; h++) {
                    const int k = mt * 2 + h;
                    float2 lv = *(const float2*)(lrow[k] + j);
                    float s0 = acc[mt][nt][2 * h + 0];
                    float s1 = acc[mt][nt][2 * h + 1];
                    if (s0 > smax[k]) { smax[k] = s0; sidx[k] = j; }
                    if (s1 > smax[k]) { smax[k] = s1; sidx[k] = j + 1; }
                    if (lv.x > lmax[k]) { lmax[k] = lv.x; lidx[k] = j; }
                    if (lv.y > lmax[k]) { lmax[k] = lv.y; lidx[k] = j + 1; }
                    float h0 = margin - (dS[k] - s0) * (dL[k] - lv.x);
                    float h1 = margin - (dS[k] - s1) * (dL[k] - lv.y);
                    const int rg = i0 + rloc[k];
                    if (j     != rg) loss += fmaxf(h0, 0.f);
                    if (j + 1 != rg) loss += fmaxf(h1, 0.f);
                }
            }
    }

    // ---- loss: warp reduce -> atomic ----
#pragma unroll
    for (int off = 16; off; off >>= 1) loss += __shfl_xor_sync(0xffffffffu, loss, off);
    if (lane == 0) atomicAdd(&g_loss, (double)loss);

    // ---- argmax: quad reduce (t4) then cross-warp merge over 4 col-groups ----
#pragma unroll
    for (int k = 0; k < 4; k++) {
#pragma unroll
        for (int o = 1; o < 4; o <<= 1) {
            float v; int ix;
            v = __shfl_xor_sync(0xffffffffu, smax[k], o); ix = __shfl_xor_sync(0xffffffffu, sidx[k], o);
            if (v > smax[k] || (v == smax[k] && ix < sidx[k])) { smax[k] = v; sidx[k] = ix; }
            v = __shfl_xor_sync(0xffffffffu, lmax[k], o); ix = __shfl_xor_sync(0xffffffffu, lidx[k], o);
            if (v > lmax[k] || (v == lmax[k] && ix < lidx[k])) { lmax[k] = v; lidx[k] = ix; }
        }
    }

    // merge arrays overlay on A smem (done with mainloop)
    __syncthreads();
    float* ms = (float*)sm;                 // [4][128] sim max
    int*   mi = (int*)(sm + 2048);          // [4][128] sim idx
    float* Ls = (float*)(sm + 4096);        // [4][128] lab max
    int*   Li = (int*)(sm + 6144);          // [4][128] lab idx
    if (t4 == 0) {
#pragma unroll
        for (int k = 0; k < 4; k++) {
            ms[colgrp * 128 + rloc[k]] = smax[k];
            mi[colgrp * 128 + rloc[k]] = sidx[k];
            Ls[colgrp * 128 + rloc[k]] = lmax[k];
            Li[colgrp * 128 + rloc[k]] = lidx[k];
        }
    }
    __syncthreads();
    int match = 0;
    if (tid < 128) {
        float bs = -INFINITY, bl = -INFINITY;
        int bsi = 0, bli = 0;
#pragma unroll
        for (int c = 0; c < 4; c++) {
            float v = ms[c * 128 + tid]; int ix = mi[c * 128 + tid];
            if (v > bs || (v == bs && ix < bsi)) { bs = v; bsi = ix; }
            float u = Ls[c * 128 + tid]; int jx = Li[c * 128 + tid];
            if (u > bl || (u == bl && jx < bli)) { bl = u; bli = jx; }
        }
        match = (bsi == bli);
    }
    match = __reduce_add_sync(0xffffffffu, match);
    if (lane == 0 && tid < 128 && match) atomicAdd(&g_count, match);
}

__global__ void k_final(float* out, int nout) {
    if (threadIdx.x == 0) {
        if (nout > 0) out[0] = (float)g_loss;
        if (nout > 1) out[1] = (float)g_count;
    }
}

extern "C" void kernel_launch(void* const* d_in, const int* in_sizes, int n_in,
                              void* d_out, int out_size) {
    const float* out_matrix = (const float*)d_in[0];
    const float* label      = (const float*)d_in[1];
    const float* margin     = (const float*)d_in[2];
    float* out = (float*)d_out;

    cudaFuncSetAttribute(k_gemm, cudaFuncAttributeMaxDynamicSharedMemorySize, SM_TOTAL);

    dim3 gn(NN, 2);
    k_norm<<<gn, 256>>>(out_matrix);
    k_diag<<<FF * NN / 8, 256>>>(label);
    dim3 gm(NTILE, FF);
    k_gemm<<<gm, THREADS, SM_TOTAL>>>(label, margin);
    k_final<<<1, 32>>>(out, out_size);
}

// round 6
// speedup vs baseline: 3.9096x; 1.0270x over previous
#include <cuda_runtime.h>
#include <cuda_bf16.h>
#include <math.h>
#include <stdint.h>

#define NN 2048
#define DD 128
#define FF 8
#define TM 64              // i-rows per CTA
#define TNJ 64             // j-cols per tile
#define NTILE (NN / TNJ)   // 32
#define THREADS 256

__device__ __nv_bfloat16 g_qh[FF * NN * DD];
__device__ __nv_bfloat16 g_ql[FF * NN * DD];
__device__ __nv_bfloat16 g_dh[FF * NN * DD];
__device__ __nv_bfloat16 g_dl[FF * NN * DD];
__device__ double g_loss;
__device__ int    g_count;

__device__ __forceinline__ uint32_t smem_u32(const void* p) {
    uint32_t a;
    asm("{ .reg .u64 t; cvta.to.shared.u64 t, %1; cvt.u32.u64 %0, t; }" : "=r"(a) : "l"(p));
    return a;
}
__device__ __forceinline__ void cpa16(uint32_t dst, const void* src) {
    asm volatile("cp.async.cg.shared.global [%0], [%1], 16;" :: "r"(dst), "l"(src) : "memory");
}
#define CP_COMMIT() asm volatile("cp.async.commit_group;" ::: "memory")
#define CP_WAIT0()  asm volatile("cp.async.wait_group 0;" ::: "memory")

#define LDSM4(r, addr) \
    asm volatile("ldmatrix.sync.aligned.m8n8.x4.shared.b16 {%0,%1,%2,%3}, [%4];" \
                 : "=r"((r)[0]), "=r"((r)[1]), "=r"((r)[2]), "=r"((r)[3]) : "r"(addr))
#define LDSM2(r, addr) \
    asm volatile("ldmatrix.sync.aligned.m8n8.x2.shared.b16 {%0,%1}, [%2];" \
                 : "=r"((r)[0]), "=r"((r)[1]) : "r"(addr))

__device__ __forceinline__ void mma_bf16(float* c, const uint32_t* a, const uint32_t* b) {
    asm volatile(
        "mma.sync.aligned.m16n8k16.row.col.f32.bf16.bf16.f32 "
        "{%0,%1,%2,%3}, {%4,%5,%6,%7}, {%8,%9}, {%0,%1,%2,%3};"
        : "+f"(c[0]), "+f"(c[1]), "+f"(c[2]), "+f"(c[3])
        : "r"(a[0]), "r"(a[1]), "r"(a[2]), "r"(a[3]), "r"(b[0]), "r"(b[1]));
}

__device__ __forceinline__ uint32_t swz(int row, int chunk) {
    return (uint32_t)(row * 256 + ((chunk ^ (row & 7)) << 4));
}

// SMEM: AH 16K | AL 16K | B0(h16K,l16K) | B1(h16K,l16K) | diag 512B = 98,816 B
#define SM_AH   0
#define SM_AL   16384
#define SM_B0   32768
#define SM_BSTR 32768
#define SM_DIAG 98304
#define SM_TOTAL (98304 + 512)

// ---------------- prep ----------------
__global__ void k_norm(const float* __restrict__ in0) {
    __shared__ float sd[DD * FF];
    int s = blockIdx.y, n = blockIdx.x;
    int tid = threadIdx.x;
    if (s == 0 && n == 0 && tid == 0) { g_loss = 0.0; g_count = 0; }
    int f = tid >> 5, lane = tid & 31;
    const float4* base = (const float4*)(in0 + ((size_t)(s * NN + n)) * DD * FF);
    *(float4*)&sd[tid * 4] = base[tid];
    __syncthreads();
    float v[4], ssq = 0.f;
#pragma unroll
    for (int k = 0; k < 4; k++) {
        v[k] = sd[(lane + 32 * k) * FF + f];
        ssq += v[k] * v[k];
    }
#pragma unroll
    for (int off = 16; off; off >>= 1) ssq += __shfl_xor_sync(0xffffffffu, ssq, off);
    float rn = 1.0f / sqrtf(ssq);
    __nv_bfloat16* oh = (s == 0 ? g_qh : g_dh) + ((size_t)(f * NN + n)) * DD;
    __nv_bfloat16* ol = (s == 0 ? g_ql : g_dl) + ((size_t)(f * NN + n)) * DD;
#pragma unroll
    for (int k = 0; k < 4; k++) {
        float x = v[k] * rn;
        __nv_bfloat16 h = __float2bfloat16(x);
        oh[lane + 32 * k] = h;
        ol[lane + 32 * k] = __float2bfloat16(x - __bfloat162float(h));
    }
}

__device__ __forceinline__ void load_tile_async(uint32_t smbase, const __nv_bfloat16* src, int tid) {
#pragma unroll
    for (int it = 0; it < (TM * 16) / THREADS; it++) {
        int idx = tid + it * THREADS;
        int row = idx >> 4, c = idx & 15;
        cpa16(smbase + swz(row, c), src + row * DD + c * 8);
    }
}

// ---------------- main ----------------
__global__ void __launch_bounds__(THREADS, 2) k_gemm(const float* __restrict__ label,
                                                     const float* __restrict__ pmargin) {
    extern __shared__ __align__(1024) char sm[];
    const uint32_t smb = smem_u32(sm);
    const int tid = threadIdx.x;
    const int w = tid >> 5, lane = tid & 31;
    const int g = lane >> 2, t4 = lane & 3;
    const int rowgrp = w >> 2, colgrp = w & 3;     // 2 x 4 warp grid
    const int f = blockIdx.y;
    const int i0 = blockIdx.x * TM;
    const float margin = *pmargin;
    const size_t fb = (size_t)f * NN;
    float* sdS = (float*)(sm + SM_DIAG);
    float* sdL = sdS + TM;

    // async A + B0
    load_tile_async(smb + SM_AH, g_qh + (fb + i0) * DD, tid);
    load_tile_async(smb + SM_AL, g_ql + (fb + i0) * DD, tid);
    load_tile_async(smb + SM_B0,         g_dh + fb * DD, tid);
    load_tile_async(smb + SM_B0 + 16384, g_dl + fb * DD, tid);
    CP_COMMIT();

    // fused diag: warp w -> rows [w*8, w*8+8)
    {
        const int d = lane * 4;
#pragma unroll 1
        for (int r8 = 0; r8 < 8; r8++) {
            int row = w * 8 + r8;
            const __nv_bfloat16* qh = g_qh + (fb + i0 + row) * DD;
            const __nv_bfloat16* ql = g_ql + (fb + i0 + row) * DD;
            const __nv_bfloat16* dh = g_dh + (fb + i0 + row) * DD;
            const __nv_bfloat16* dl = g_dl + (fb + i0 + row) * DD;
            float s = 0.f;
#pragma unroll
            for (int u = 0; u < 4; u++) {
                float a = __bfloat162float(qh[d + u]), al_ = __bfloat162float(ql[d + u]);
                float b = __bfloat162float(dh[d + u]), bl_ = __bfloat162float(dl[d + u]);
                s += a * b + a * bl_ + al_ * b;
            }
#pragma unroll
            for (int off = 16; off; off >>= 1) s += __shfl_xor_sync(0xffffffffu, s, off);
            if (lane == 0) {
                sdS[row] = s;
                sdL[row] = label[(fb + i0 + row) * NN + (i0 + row)];
            }
        }
    }

    CP_WAIT0();
    __syncthreads();     // A, B0 ready; sdS/sdL visible

    // per-thread rows: rloc[k] = rowgrp*32 + mt*16 + g + h*8, k = mt*2+h
    int rloc[4];
    float dS[4], dL[4];
    uint32_t loff[4];    // byte offset of label row
#pragma unroll
    for (int mt = 0; mt < 2; mt++)
#pragma unroll
        for (int h = 0; h < 2; h++) {
            int k = mt * 2 + h;
            rloc[k] = rowgrp * 32 + mt * 16 + g + h * 8;
            dS[k] = sdS[rloc[k]];
            dL[k] = sdL[rloc[k]];
            loff[k] = (uint32_t)(((fb + i0 + rloc[k]) * NN) * 4);
        }

    float smax[4], lmax[4];
    int sidx[4], lidx[4];
#pragma unroll
    for (int k = 0; k < 4; k++) {
        smax[k] = -INFINITY; lmax[k] = -INFINITY; sidx[k] = 0; lidx[k] = 0;
    }
    float loss = 0.f;

    const int arow0 = rowgrp * 32 + (lane & 15);
    const int ahalf = lane >> 4;
    const int brow = lane & 7;
    const int bhalf = (lane >> 3) & 1;
    const char* labc = (const char*)label;

#pragma unroll 1
    for (int t = 0; t < NTILE; t++) {
        // prefetch next B before MMA
        if (t + 1 < NTILE) {
            uint32_t nb = smb + SM_B0 + (uint32_t)((t + 1) & 1) * SM_BSTR;
            load_tile_async(nb,         g_dh + (fb + (size_t)(t + 1) * TNJ) * DD, tid);
            load_tile_async(nb + 16384, g_dl + (fb + (size_t)(t + 1) * TNJ) * DD, tid);
            CP_COMMIT();
        }
        const uint32_t bb = smb + SM_B0 + (uint32_t)(t & 1) * SM_BSTR;

        float acc[2][2][4];
#pragma unroll
        for (int mt = 0; mt < 2; mt++)
#pragma unroll
            for (int nt = 0; nt < 2; nt++)
#pragma unroll
                for (int u = 0; u < 4; u++) acc[mt][nt][u] = 0.f;

#pragma unroll
        for (int ks = 0; ks < 8; ks++) {
            uint32_t ah0[4], al0[4], ah1[4], al1[4];
            uint32_t aoff0 = swz(arow0,      2 * ks + ahalf);
            uint32_t aoff1 = swz(arow0 + 16, 2 * ks + ahalf);
            LDSM4(ah0, smb + SM_AH + aoff0);
            LDSM4(ah1, smb + SM_AH + aoff1);
            LDSM4(al0, smb + SM_AL + aoff0);
            LDSM4(al1, smb + SM_AL + aoff1);
#pragma unroll
            for (int nt = 0; nt < 2; nt++) {
                uint32_t bh[2], bl[2];
                int ntg = colgrp * 2 + nt;
                uint32_t boff = swz(8 * ntg + brow, 2 * ks + bhalf);
                LDSM2(bh, bb + boff);
                LDSM2(bl, bb + 16384 + boff);
                mma_bf16(acc[0][nt], ah0, bh);
                mma_bf16(acc[1][nt], ah1, bh);
                mma_bf16(acc[0][nt], ah0, bl);
                mma_bf16(acc[1][nt], ah1, bl);
                mma_bf16(acc[0][nt], al0, bh);
                mma_bf16(acc[1][nt], al1, bh);
            }
        }

        // epilogue: no diagonal predicate (diag contributes exactly `margin`,
        // corrected in k_final: (dL - l) == 0 bitwise at j == i)
        const int j0 = t * TNJ;
#pragma unroll
        for (int mt = 0; mt < 2; mt++)
#pragma unroll
            for (int nt = 0; nt < 2; nt++) {
                const int j = j0 + (colgrp * 2 + nt) * 8 + t4 * 2;
#pragma unroll
                for (int h = 0; h < 2; h++) {
                    const int k = mt * 2 + h;
                    float2 lv = *(const float2*)(labc + loff[k] + (uint32_t)j * 4);
                    float s0 = acc[mt][nt][2 * h + 0];
                    float s1 = acc[mt][nt][2 * h + 1];
                    if (s0 > smax[k]) { smax[k] = s0; sidx[k] = j; }
                    if (s1 > smax[k]) { smax[k] = s1; sidx[k] = j + 1; }
                    if (lv.x > lmax[k]) { lmax[k] = lv.x; lidx[k] = j; }
                    if (lv.y > lmax[k]) { lmax[k] = lv.y; lidx[k] = j + 1; }
                    float h0 = margin - (dS[k] - s0) * (dL[k] - lv.x);
                    float h1 = margin - (dS[k] - s1) * (dL[k] - lv.y);
                    loss += fmaxf(h0, 0.f);
                    loss += fmaxf(h1, 0.f);
                }
            }

        if (t + 1 < NTILE) {
            CP_WAIT0();          // B(t+1) landed during MMA+epilogue
            __syncthreads();     // all warps done reading buffer t -> reusable at t+2
        }
    }

    // ---- loss ----
#pragma unroll
    for (int off = 16; off; off >>= 1) loss += __shfl_xor_sync(0xffffffffu, loss, off);
    if (lane == 0) atomicAdd(&g_loss, (double)loss);

    // ---- argmax: quad reduce then cross-colgrp merge ----
#pragma unroll
    for (int k = 0; k < 4; k++) {
#pragma unroll
        for (int o = 1; o < 4; o <<= 1) {
            float v; int ix;
            v = __shfl_xor_sync(0xffffffffu, smax[k], o); ix = __shfl_xor_sync(0xffffffffu, sidx[k], o);
            if (v > smax[k] || (v == smax[k] && ix < sidx[k])) { smax[k] = v; sidx[k] = ix; }
            v = __shfl_xor_sync(0xffffffffu, lmax[k], o); ix = __shfl_xor_sync(0xffffffffu, lidx[k], o);
            if (v > lmax[k] || (v == lmax[k] && ix < lidx[k])) { lmax[k] = v; lidx[k] = ix; }
        }
    }

    __syncthreads();                         // A smem dead -> reuse for merge
    float* ms = (float*)sm;                  // [4][64]
    int*   mi = (int*)(sm + 1024);
    float* Ls = (float*)(sm + 2048);
    int*   Li = (int*)(sm + 3072);
    if (t4 == 0) {
#pragma unroll
        for (int k = 0; k < 4; k++) {
            ms[colgrp * TM + rloc[k]] = smax[k];
            mi[colgrp * TM + rloc[k]] = sidx[k];
            Ls[colgrp * TM + rloc[k]] = lmax[k];
            Li[colgrp * TM + rloc[k]] = lidx[k];
        }
    }
    __syncthreads();
    int match = 0;
    if (tid < TM) {
        float bs = -INFINITY, bl = -INFINITY;
        int bsi = 0, bli = 0;
#pragma unroll
        for (int c = 0; c < 4; c++) {
            float v = ms[c * TM + tid]; int ix = mi[c * TM + tid];
            if (v > bs || (v == bs && ix < bsi)) { bs = v; bsi = ix; }
            float u = Ls[c * TM + tid]; int jx = Li[c * TM + tid];
            if (u > bl || (u == bl && jx < bli)) { bl = u; bli = jx; }
        }
        match = (bsi == bli);
    }
    match = __reduce_add_sync(0xffffffffu, match);
    if (lane == 0 && w < (TM / 32) && match) atomicAdd(&g_count, match);
}

__global__ void k_final(float* out, int nout, const float* pmargin) {
    if (threadIdx.x == 0) {
        double m = (double)(*pmargin);
        if (nout > 0) out[0] = (float)(g_loss - (double)(FF * NN) * m);
        if (nout > 1) out[1] = (float)g_count;
    }
}

extern "C" void kernel_launch(void* const* d_in, const int* in_sizes, int n_in,
                              void* d_out, int out_size) {
    const float* out_matrix = (const float*)d_in[0];
    const float* label      = (const float*)d_in[1];
    const float* margin     = (const float*)d_in[2];
    float* out = (float*)d_out;

    cudaFuncSetAttribute(k_gemm, cudaFuncAttributeMaxDynamicSharedMemorySize, SM_TOTAL);

    dim3 gn(NN, 2);
    k_norm<<<gn, 256>>>(out_matrix);
    dim3 gm(NN / TM, FF);
    k_gemm<<<gm, THREADS, SM_TOTAL>>>(label, margin);
    k_final<<<1, 32>>>(out, out_size, margin);
}

// round 7
// speedup vs baseline: 5.3291x; 1.3631x over previous
#include <cuda_runtime.h>
#include <cuda_fp16.h>
#include <math.h>
#include <stdint.h>

#define NN 2048
#define DD 128
#define FF 8
#define TM 64               // i-rows per CTA
#define TNJ 128             // j-cols per tile
#define NTILE (NN / TNJ)    // 16
#define THREADS 256

__device__ __half g_qh[FF * NN * DD];
__device__ __half g_ql[FF * NN * DD];
__device__ __half g_dh[FF * NN * DD];
__device__ double g_loss;
__device__ int    g_count;

__device__ __forceinline__ uint32_t smem_u32(const void* p) {
    uint32_t a;
    asm("{ .reg .u64 t; cvta.to.shared.u64 t, %1; cvt.u32.u64 %0, t; }" : "=r"(a) : "l"(p));
    return a;
}
__device__ __forceinline__ void cpa16(uint32_t dst, const void* src) {
    asm volatile("cp.async.cg.shared.global [%0], [%1], 16;" :: "r"(dst), "l"(src) : "memory");
}
#define CP_COMMIT() asm volatile("cp.async.commit_group;" ::: "memory")
#define CP_WAIT0()  asm volatile("cp.async.wait_group 0;" ::: "memory")

#define LDSM4(r, addr) \
    asm volatile("ldmatrix.sync.aligned.m8n8.x4.shared.b16 {%0,%1,%2,%3}, [%4];" \
                 : "=r"((r)[0]), "=r"((r)[1]), "=r"((r)[2]), "=r"((r)[3]) : "r"(addr))
#define LDSM2(r, addr) \
    asm volatile("ldmatrix.sync.aligned.m8n8.x2.shared.b16 {%0,%1}, [%2];" \
                 : "=r"((r)[0]), "=r"((r)[1]) : "r"(addr))

__device__ __forceinline__ void mma_f16(float* c, const uint32_t* a, const uint32_t* b) {
    asm volatile(
        "mma.sync.aligned.m16n8k16.row.col.f32.f16.f16.f32 "
        "{%0,%1,%2,%3}, {%4,%5,%6,%7}, {%8,%9}, {%0,%1,%2,%3};"
        : "+f"(c[0]), "+f"(c[1]), "+f"(c[2]), "+f"(c[3])
        : "r"(a[0]), "r"(a[1]), "r"(a[2]), "r"(a[3]), "r"(b[0]), "r"(b[1]));
}

__device__ __forceinline__ uint32_t swz(int row, int chunk) {
    return (uint32_t)(row * 256 + ((chunk ^ (row & 7)) << 4));
}

// SMEM: AH 16K | AL 16K | B0 32K | B1 32K | diag 512B
#define SM_AH   0
#define SM_AL   16384
#define SM_B0   32768
#define SM_BSTR 32768
#define SM_DIAG 98304
#define SM_TOTAL (98304 + 512)

// ---------------- prep: normalize + fp16 split ----------------
// in0 [2, N, D, F]; q -> (hi, lo), d -> hi only
__global__ void k_norm(const float* __restrict__ in0) {
    __shared__ float sd[DD * 9 + 9];   // pitch 9: conflict-free strided reads
    int s = blockIdx.y, n = blockIdx.x;
    int tid = threadIdx.x;
    if (s == 0 && n == 0 && tid == 0) { g_loss = 0.0; g_count = 0; }
    int f = tid >> 5, lane = tid & 31;
    const float4* base = (const float4*)(in0 + ((size_t)(s * NN + n)) * DD * FF);
    float4 v4 = base[tid];
    {
        int e = tid * 4;
        sd[((e + 0) >> 3) * 9 + ((e + 0) & 7)] = v4.x;
        sd[((e + 1) >> 3) * 9 + ((e + 1) & 7)] = v4.y;
        sd[((e + 2) >> 3) * 9 + ((e + 2) & 7)] = v4.z;
        sd[((e + 3) >> 3) * 9 + ((e + 3) & 7)] = v4.w;
    }
    __syncthreads();
    float v[4], ssq = 0.f;
#pragma unroll
    for (int k = 0; k < 4; k++) {
        v[k] = sd[(lane + 32 * k) * 9 + f];
        ssq += v[k] * v[k];
    }
#pragma unroll
    for (int off = 16; off; off >>= 1) ssq += __shfl_xor_sync(0xffffffffu, ssq, off);
    float rn = 1.0f / sqrtf(ssq);
    if (s == 0) {
        __half* oh = g_qh + ((size_t)(f * NN + n)) * DD;
        __half* ol = g_ql + ((size_t)(f * NN + n)) * DD;
#pragma unroll
        for (int k = 0; k < 4; k++) {
            float x = v[k] * rn;
            __half h = __float2half_rn(x);
            oh[lane + 32 * k] = h;
            ol[lane + 32 * k] = __float2half_rn(x - __half2float(h));
        }
    } else {
        __half* oh = g_dh + ((size_t)(f * NN + n)) * DD;
#pragma unroll
        for (int k = 0; k < 4; k++)
            oh[lane + 32 * k] = __float2half_rn(v[k] * rn);
    }
}

template <int ROWS>
__device__ __forceinline__ void load_tile_async(uint32_t smbase, const __half* src, int tid) {
#pragma unroll
    for (int it = 0; it < (ROWS * 16) / THREADS; it++) {
        int idx = tid + it * THREADS;
        int row = idx >> 4, c = idx & 15;
        cpa16(smbase + swz(row, c), src + row * DD + c * 8);
    }
}

// ---------------- main ----------------
__global__ void __launch_bounds__(THREADS, 2) k_gemm(const float* __restrict__ label,
                                                     const float* __restrict__ pmargin) {
    extern __shared__ __align__(1024) char sm[];
    const uint32_t smb = smem_u32(sm);
    const int tid = threadIdx.x;
    const int w = tid >> 5, lane = tid & 31;
    const int g = lane >> 2, t4 = lane & 3;
    const int rowgrp = w >> 2, colgrp = w & 3;     // 2 x 4 warp grid: 32 rows x 32 cols each
    const int f = blockIdx.y;
    const int i0 = blockIdx.x * TM;
    const float margin = *pmargin;
    const size_t fb = (size_t)f * NN;
    float* sdS = (float*)(sm + SM_DIAG);
    float* sdL = sdS + TM;

    load_tile_async<TM>(smb + SM_AH, g_qh + (fb + i0) * DD, tid);
    load_tile_async<TM>(smb + SM_AL, g_ql + (fb + i0) * DD, tid);
    load_tile_async<TNJ>(smb + SM_B0, g_dh + fb * DD, tid);
    CP_COMMIT();

    // fused diag: dS = q . dh (fp32), consistent with MMA arithmetic
    {
        const int d = lane * 4;
#pragma unroll 1
        for (int r8 = 0; r8 < 8; r8++) {
            int row = w * 8 + r8;
            const __half* qh = g_qh + (fb + i0 + row) * DD;
            const __half* ql = g_ql + (fb + i0 + row) * DD;
            const __half* dh = g_dh + (fb + i0 + row) * DD;
            float s = 0.f;
#pragma unroll
            for (int u = 0; u < 4; u++) {
                float a = __half2float(qh[d + u]) + __half2float(ql[d + u]);
                s += a * __half2float(dh[d + u]);
            }
#pragma unroll
            for (int off = 16; off; off >>= 1) s += __shfl_xor_sync(0xffffffffu, s, off);
            if (lane == 0) {
                sdS[row] = s;
                sdL[row] = label[(fb + i0 + row) * NN + (i0 + row)];
            }
        }
    }

    CP_WAIT0();
    __syncthreads();

    int rloc[4];
    float dS[4], dL[4];
    uint32_t loff[4];
#pragma unroll
    for (int mt = 0; mt < 2; mt++)
#pragma unroll
        for (int h = 0; h < 2; h++) {
            int k = mt * 2 + h;
            rloc[k] = rowgrp * 32 + mt * 16 + g + h * 8;
            dS[k] = sdS[rloc[k]];
            dL[k] = sdL[rloc[k]];
            loff[k] = (uint32_t)(((fb + i0 + rloc[k]) * NN) * 4);
        }

    float smax[4], lmax[4];
    int sidx[4], lidx[4];
#pragma unroll
    for (int k = 0; k < 4; k++) {
        smax[k] = -INFINITY; lmax[k] = -INFINITY; sidx[k] = 0; lidx[k] = 0;
    }
    float loss = 0.f;

    const int arow0 = rowgrp * 32 + (lane & 15);
    const int ahalf = lane >> 4;
    const int brow = lane & 7;
    const int bhalf = (lane >> 3) & 1;
    const char* labc = (const char*)label;

#pragma unroll 1
    for (int t = 0; t < NTILE; t++) {
        if (t + 1 < NTILE) {
            uint32_t nb = smb + SM_B0 + (uint32_t)((t + 1) & 1) * SM_BSTR;
            load_tile_async<TNJ>(nb, g_dh + (fb + (size_t)(t + 1) * TNJ) * DD, tid);
            CP_COMMIT();
        }
        const uint32_t bb = smb + SM_B0 + (uint32_t)(t & 1) * SM_BSTR;
        const int j0 = t * TNJ;

        // label prefetch into registers (hides DRAM latency under MMAs)
        float2 lv[2][4][2];
#pragma unroll
        for (int mt = 0; mt < 2; mt++)
#pragma unroll
            for (int nt = 0; nt < 4; nt++) {
                const int j = j0 + (colgrp * 4 + nt) * 8 + t4 * 2;
#pragma unroll
                for (int h = 0; h < 2; h++)
                    lv[mt][nt][h] = *(const float2*)(labc + loff[mt * 2 + h] + (uint32_t)j * 4);
            }

        float acc[2][4][4];
#pragma unroll
        for (int mt = 0; mt < 2; mt++)
#pragma unroll
            for (int nt = 0; nt < 4; nt++)
#pragma unroll
                for (int u = 0; u < 4; u++) acc[mt][nt][u] = 0.f;

#pragma unroll
        for (int ks = 0; ks < 8; ks++) {
            uint32_t ah0[4], al0[4], ah1[4], al1[4];
            uint32_t aoff0 = swz(arow0,      2 * ks + ahalf);
            uint32_t aoff1 = swz(arow0 + 16, 2 * ks + ahalf);
            LDSM4(ah0, smb + SM_AH + aoff0);
            LDSM4(ah1, smb + SM_AH + aoff1);
            LDSM4(al0, smb + SM_AL + aoff0);
            LDSM4(al1, smb + SM_AL + aoff1);
#pragma unroll
            for (int nt = 0; nt < 4; nt++) {
                uint32_t bh[2];
                uint32_t boff = swz(8 * (colgrp * 4 + nt) + brow, 2 * ks + bhalf);
                LDSM2(bh, bb + boff);
                mma_f16(acc[0][nt], ah0, bh);
                mma_f16(acc[1][nt], ah1, bh);
                mma_f16(acc[0][nt], al0, bh);
                mma_f16(acc[1][nt], al1, bh);
            }
        }

        // epilogue (diagonal term contributes exactly `margin` since dL - l == 0; fixed in k_final)
#pragma unroll
        for (int mt = 0; mt < 2; mt++)
#pragma unroll
            for (int nt = 0; nt < 4; nt++) {
                const int j = j0 + (colgrp * 4 + nt) * 8 + t4 * 2;
#pragma unroll
                for (int h = 0; h < 2; h++) {
                    const int k = mt * 2 + h;
                    float2 l2 = lv[mt][nt][h];
                    float s0 = acc[mt][nt][2 * h + 0];
                    float s1 = acc[mt][nt][2 * h + 1];
                    if (s0 > smax[k]) { smax[k] = s0; sidx[k] = j; }
                    if (s1 > smax[k]) { smax[k] = s1; sidx[k] = j + 1; }
                    if (l2.x > lmax[k]) { lmax[k] = l2.x; lidx[k] = j; }
                    if (l2.y > lmax[k]) { lmax[k] = l2.y; lidx[k] = j + 1; }
                    loss += fmaxf(margin - (dS[k] - s0) * (dL[k] - l2.x), 0.f);
                    loss += fmaxf(margin - (dS[k] - s1) * (dL[k] - l2.y), 0.f);
                }
            }

        if (t + 1 < NTILE) {
            CP_WAIT0();
            __syncthreads();
        }
    }

    // ---- loss ----
#pragma unroll
    for (int off = 16; off; off >>= 1) loss += __shfl_xor_sync(0xffffffffu, loss, off);
    if (lane == 0) atomicAdd(&g_loss, (double)loss);

    // ---- argmax: quad reduce then cross-colgrp merge ----
#pragma unroll
    for (int k = 0; k < 4; k++) {
#pragma unroll
        for (int o = 1; o < 4; o <<= 1) {
            float v; int ix;
            v = __shfl_xor_sync(0xffffffffu, smax[k], o); ix = __shfl_xor_sync(0xffffffffu, sidx[k], o);
            if (v > smax[k] || (v == smax[k] && ix < sidx[k])) { smax[k] = v; sidx[k] = ix; }
            v = __shfl_xor_sync(0xffffffffu, lmax[k], o); ix = __shfl_xor_sync(0xffffffffu, lidx[k], o);
            if (v > lmax[k] || (v == lmax[k] && ix < lidx[k])) { lmax[k] = v; lidx[k] = ix; }
        }
    }

    __syncthreads();
    float* ms = (float*)sm;
    int*   mi = (int*)(sm + 1024);
    float* Ls = (float*)(sm + 2048);
    int*   Li = (int*)(sm + 3072);
    if (t4 == 0) {
#pragma unroll
        for (int k = 0; k < 4; k++) {
            ms[colgrp * TM + rloc[k]] = smax[k];
            mi[colgrp * TM + rloc[k]] = sidx[k];
            Ls[colgrp * TM + rloc[k]] = lmax[k];
            Li[colgrp * TM + rloc[k]] = lidx[k];
        }
    }
    __syncthreads();
    int match = 0;
    if (tid < TM) {
        float bs = -INFINITY, bl = -INFINITY;
        int bsi = 0, bli = 0;
#pragma unroll
        for (int c = 0; c < 4; c++) {
            float v = ms[c * TM + tid]; int ix = mi[c * TM + tid];
            if (v > bs || (v == bs && ix < bsi)) { bs = v; bsi = ix; }
            float u = Ls[c * TM + tid]; int jx = Li[c * TM + tid];
            if (u > bl || (u == bl && jx < bli)) { bl = u; bli = jx; }
        }
        match = (bsi == bli);
    }
    match = __reduce_add_sync(0xffffffffu, match);
    if (lane == 0 && w < (TM / 32) && match) atomicAdd(&g_count, match);
}

__global__ void k_final(float* out, int nout, const float* pmargin) {
    if (threadIdx.x == 0) {
        double m = (double)fmaxf(*pmargin, 0.f);
        if (nout > 0) out[0] = (float)(g_loss - (double)(FF * NN) * m);
        if (nout > 1) out[1] = (float)g_count;
    }
}

extern "C" void kernel_launch(void* const* d_in, const int* in_sizes, int n_in,
                              void* d_out, int out_size) {
    const float* out_matrix = (const float*)d_in[0];
    const float* label      = (const float*)d_in[1];
    const float* margin     = (const float*)d_in[2];
    float* out = (float*)d_out;

    cudaFuncSetAttribute(k_gemm, cudaFuncAttributeMaxDynamicSharedMemorySize, SM_TOTAL);

    dim3 gn(NN, 2);
    k_norm<<<gn, 256>>>(out_matrix);
    dim3 gm(NN / TM, FF);
    k_gemm<<<gm, THREADS, SM_TOTAL>>>(label, margin);
    k_final<<<1, 32>>>(out, out_size, margin);
}

// round 8
// speedup vs baseline: 6.0322x; 1.1319x over previous
#include <cuda_runtime.h>
#include <cuda_fp16.h>
#include <math.h>
#include <stdint.h>

#define NN 2048
#define DD 128
#define FF 8
#define TM 64               // i-rows per CTA
#define TNJ 128             // j-cols per tile
#define NTILE (NN / TNJ)    // 16
#define THREADS 256
#define NCTAS ((NN / TM) * FF)   // 256

__device__ __half g_qh[FF * NN * DD];
__device__ __half g_dh[FF * NN * DD];
__device__ double g_loss;
__device__ int    g_count;
__device__ int    g_done;

__device__ __forceinline__ uint32_t smem_u32(const void* p) {
    uint32_t a;
    asm("{ .reg .u64 t; cvta.to.shared.u64 t, %1; cvt.u32.u64 %0, t; }" : "=r"(a) : "l"(p));
    return a;
}
__device__ __forceinline__ void cpa16(uint32_t dst, const void* src) {
    asm volatile("cp.async.cg.shared.global [%0], [%1], 16;" :: "r"(dst), "l"(src) : "memory");
}
#define CP_COMMIT() asm volatile("cp.async.commit_group;" ::: "memory")
#define CP_WAIT0()  asm volatile("cp.async.wait_group 0;" ::: "memory")

#define LDSM4(r, addr) \
    asm volatile("ldmatrix.sync.aligned.m8n8.x4.shared.b16 {%0,%1,%2,%3}, [%4];" \
                 : "=r"((r)[0]), "=r"((r)[1]), "=r"((r)[2]), "=r"((r)[3]) : "r"(addr))

__device__ __forceinline__ void mma_f16(float* c, const uint32_t* a, const uint32_t* b) {
    asm volatile(
        "mma.sync.aligned.m16n8k16.row.col.f32.f16.f16.f32 "
        "{%0,%1,%2,%3}, {%4,%5,%6,%7}, {%8,%9}, {%0,%1,%2,%3};"
        : "+f"(c[0]), "+f"(c[1]), "+f"(c[2]), "+f"(c[3])
        : "r"(a[0]), "r"(a[1]), "r"(a[2]), "r"(a[3]), "r"(b[0]), "r"(b[1]));
}

__device__ __forceinline__ uint32_t swz(int row, int chunk) {
    return (uint32_t)(row * 256 + ((chunk ^ (row & 7)) << 4));
}

// SMEM: A 16K | B0 32K | B1 32K | diag 512B
#define SM_AH   0
#define SM_B0   16384
#define SM_BSTR 32768
#define SM_DIAG 81920
#define SM_TOTAL (81920 + 512)

// ---------------- prep: normalize -> fp16 ----------------
__global__ void k_norm(const float* __restrict__ in0) {
    __shared__ float sd[DD * 9 + 9];
    int s = blockIdx.y, n = blockIdx.x;
    int tid = threadIdx.x;
    int f = tid >> 5, lane = tid & 31;
    const float4* base = (const float4*)(in0 + ((size_t)(s * NN + n)) * DD * FF);
    float4 v4 = base[tid];
    {
        int e = tid * 4;
        sd[((e + 0) >> 3) * 9 + ((e + 0) & 7)] = v4.x;
        sd[((e + 1) >> 3) * 9 + ((e + 1) & 7)] = v4.y;
        sd[((e + 2) >> 3) * 9 + ((e + 2) & 7)] = v4.z;
        sd[((e + 3) >> 3) * 9 + ((e + 3) & 7)] = v4.w;
    }
    __syncthreads();
    float v[4], ssq = 0.f;
#pragma unroll
    for (int k = 0; k < 4; k++) {
        v[k] = sd[(lane + 32 * k) * 9 + f];
        ssq += v[k] * v[k];
    }
#pragma unroll
    for (int off = 16; off; off >>= 1) ssq += __shfl_xor_sync(0xffffffffu, ssq, off);
    float rn = 1.0f / sqrtf(ssq);
    __half* oh = (s == 0 ? g_qh : g_dh) + ((size_t)(f * NN + n)) * DD;
#pragma unroll
    for (int k = 0; k < 4; k++)
        oh[lane + 32 * k] = __float2half_rn(v[k] * rn);
}

template <int ROWS>
__device__ __forceinline__ void load_tile_async(uint32_t smbase, const __half* src, int tid) {
#pragma unroll
    for (int it = 0; it < (ROWS * 16) / THREADS; it++) {
        int idx = tid + it * THREADS;
        int row = idx >> 4, c = idx & 15;
        cpa16(smbase + swz(row, c), src + row * DD + c * 8);
    }
}

// ---------------- main ----------------
__global__ void __launch_bounds__(THREADS, 2) k_gemm(const float* __restrict__ label,
                                                     const float* __restrict__ pmargin,
                                                     float* __restrict__ gout, int nout) {
    extern __shared__ __align__(1024) char sm[];
    const uint32_t smb = smem_u32(sm);
    const int tid = threadIdx.x;
    const int w = tid >> 5, lane = tid & 31;
    const int g = lane >> 2, t4 = lane & 3;
    const int rowgrp = w >> 2, colgrp = w & 3;     // 2 x 4 warp grid: 32 rows x 32 cols
    const int f = blockIdx.y;
    const int i0 = blockIdx.x * TM;
    const float margin = *pmargin;
    const size_t fb = (size_t)f * NN;
    float* sdS = (float*)(sm + SM_DIAG);
    float* sdL = sdS + TM;

    load_tile_async<TM>(smb + SM_AH, g_qh + (fb + i0) * DD, tid);
    load_tile_async<TNJ>(smb + SM_B0, g_dh + fb * DD, tid);
    CP_COMMIT();

    // fused diag: dS = qh . dh (fp32)
    {
        const int d = lane * 4;
#pragma unroll 1
        for (int r8 = 0; r8 < 8; r8++) {
            int row = w * 8 + r8;
            const __half* qh = g_qh + (fb + i0 + row) * DD;
            const __half* dh = g_dh + (fb + i0 + row) * DD;
            float s = 0.f;
#pragma unroll
            for (int u = 0; u < 4; u++)
                s += __half2float(qh[d + u]) * __half2float(dh[d + u]);
#pragma unroll
            for (int off = 16; off; off >>= 1) s += __shfl_xor_sync(0xffffffffu, s, off);
            if (lane == 0) {
                sdS[row] = s;
                sdL[row] = label[(fb + i0 + row) * NN + (i0 + row)];
            }
        }
    }

    CP_WAIT0();
    __syncthreads();

    int rloc[4];
    float dS[4], dL[4];
    uint32_t loff[4];
#pragma unroll
    for (int mt = 0; mt < 2; mt++)
#pragma unroll
        for (int h = 0; h < 2; h++) {
            int k = mt * 2 + h;
            rloc[k] = rowgrp * 32 + mt * 16 + g + h * 8;
            dS[k] = sdS[rloc[k]];
            dL[k] = sdL[rloc[k]];
            loff[k] = (uint32_t)(((fb + i0 + rloc[k]) * NN) * 4);
        }

    float smax[4], lmax[4];
    int sidx[4], lidx[4];
#pragma unroll
    for (int k = 0; k < 4; k++) {
        smax[k] = -INFINITY; lmax[k] = -INFINITY; sidx[k] = 0; lidx[k] = 0;
    }
    float loss = 0.f;

    const int arow0 = rowgrp * 32 + (lane & 15);
    const int ahalf = lane >> 4;
    // B x4 addressing: lanes 0-7 -> (nt even, khalf0), 8-15 -> (nt even, khalf1),
    //                  16-23 -> (nt odd, khalf0), 24-31 -> (nt odd, khalf1)
    const int brow = colgrp * 32 + ((lane >> 4) & 1) * 8 + (lane & 7);
    const int bhalf = (lane >> 3) & 1;
    const char* labc = (const char*)label;

#pragma unroll 1
    for (int t = 0; t < NTILE; t++) {
        if (t + 1 < NTILE) {
            uint32_t nb = smb + SM_B0 + (uint32_t)((t + 1) & 1) * SM_BSTR;
            load_tile_async<TNJ>(nb, g_dh + (fb + (size_t)(t + 1) * TNJ) * DD, tid);
            CP_COMMIT();
        }
        const uint32_t bb = smb + SM_B0 + (uint32_t)(t & 1) * SM_BSTR;
        const int j0 = t * TNJ;

        // label prefetch into registers
        float2 lv[2][4][2];
#pragma unroll
        for (int mt = 0; mt < 2; mt++)
#pragma unroll
            for (int nt = 0; nt < 4; nt++) {
                const int j = j0 + (colgrp * 4 + nt) * 8 + t4 * 2;
#pragma unroll
                for (int h = 0; h < 2; h++)
                    lv[mt][nt][h] = *(const float2*)(labc + loff[mt * 2 + h] + (uint32_t)j * 4);
            }

        float acc[2][4][4];
#pragma unroll
        for (int mt = 0; mt < 2; mt++)
#pragma unroll
            for (int nt = 0; nt < 4; nt++)
#pragma unroll
                for (int u = 0; u < 4; u++) acc[mt][nt][u] = 0.f;

#pragma unroll
        for (int ks = 0; ks < 8; ks++) {
            uint32_t ah0[4], ah1[4];
            LDSM4(ah0, smb + SM_AH + swz(arow0,      2 * ks + ahalf));
            LDSM4(ah1, smb + SM_AH + swz(arow0 + 16, 2 * ks + ahalf));
#pragma unroll
            for (int ntp = 0; ntp < 2; ntp++) {
                uint32_t bfr[4];
                LDSM4(bfr, bb + swz(brow + ntp * 16, 2 * ks + bhalf));
                mma_f16(acc[0][2 * ntp + 0], ah0, bfr + 0);
                mma_f16(acc[1][2 * ntp + 0], ah1, bfr + 0);
                mma_f16(acc[0][2 * ntp + 1], ah0, bfr + 2);
                mma_f16(acc[1][2 * ntp + 1], ah1, bfr + 2);
            }
        }

        // epilogue (diagonal contributes exactly `margin`; corrected at the end)
#pragma unroll
        for (int mt = 0; mt < 2; mt++)
#pragma unroll
            for (int nt = 0; nt < 4; nt++) {
                const int j = j0 + (colgrp * 4 + nt) * 8 + t4 * 2;
#pragma unroll
                for (int h = 0; h < 2; h++) {
                    const int k = mt * 2 + h;
                    float2 l2 = lv[mt][nt][h];
                    float s0 = acc[mt][nt][2 * h + 0];
                    float s1 = acc[mt][nt][2 * h + 1];
                    if (s0 > smax[k]) { smax[k] = s0; sidx[k] = j; }
                    if (s1 > smax[k]) { smax[k] = s1; sidx[k] = j + 1; }
                    if (l2.x > lmax[k]) { lmax[k] = l2.x; lidx[k] = j; }
                    if (l2.y > lmax[k]) { lmax[k] = l2.y; lidx[k] = j + 1; }
                    loss += fmaxf(margin - (dS[k] - s0) * (dL[k] - l2.x), 0.f);
                    loss += fmaxf(margin - (dS[k] - s1) * (dL[k] - l2.y), 0.f);
                }
            }

        if (t + 1 < NTILE) {
            CP_WAIT0();
            __syncthreads();
        }
    }

    // ---- loss ----
#pragma unroll
    for (int off = 16; off; off >>= 1) loss += __shfl_xor_sync(0xffffffffu, loss, off);
    if (lane == 0) atomicAdd(&g_loss, (double)loss);

    // ---- argmax: quad reduce then cross-colgrp merge ----
#pragma unroll
    for (int k = 0; k < 4; k++) {
#pragma unroll
        for (int o = 1; o < 4; o <<= 1) {
            float v; int ix;
            v = __shfl_xor_sync(0xffffffffu, smax[k], o); ix = __shfl_xor_sync(0xffffffffu, sidx[k], o);
            if (v > smax[k] || (v == smax[k] && ix < sidx[k])) { smax[k] = v; sidx[k] = ix; }
            v = __shfl_xor_sync(0xffffffffu, lmax[k], o); ix = __shfl_xor_sync(0xffffffffu, lidx[k], o);
            if (v > lmax[k] || (v == lmax[k] && ix < lidx[k])) { lmax[k] = v; lidx[k] = ix; }
        }
    }

    __syncthreads();
    float* ms = (float*)sm;
    int*   mi = (int*)(sm + 1024);
    float* Ls = (float*)(sm + 2048);
    int*   Li = (int*)(sm + 3072);
    if (t4 == 0) {
#pragma unroll
        for (int k = 0; k < 4; k++) {
            ms[colgrp * TM + rloc[k]] = smax[k];
            mi[colgrp * TM + rloc[k]] = sidx[k];
            Ls[colgrp * TM + rloc[k]] = lmax[k];
            Li[colgrp * TM + rloc[k]] = lidx[k];
        }
    }
    __syncthreads();
    int match = 0;
    if (tid < TM) {
        float bs = -INFINITY, bl = -INFINITY;
        int bsi = 0, bli = 0;
#pragma unroll
        for (int c = 0; c < 4; c++) {
            float v = ms[c * TM + tid]; int ix = mi[c * TM + tid];
            if (v > bs || (v == bs && ix < bsi)) { bs = v; bsi = ix; }
            float u = Ls[c * TM + tid]; int jx = Li[c * TM + tid];
            if (u > bl || (u == bl && jx < bli)) { bl = u; bli = jx; }
        }
        match = (bsi == bli);
    }
    match = __reduce_add_sync(0xffffffffu, match);
    if (lane == 0 && w < (TM / 32) && match) atomicAdd(&g_count, match);

    // ---- fused finalize: last CTA writes output and resets accumulators ----
    __syncthreads();
    if (tid == 0) {
        __threadfence();
        int old = atomicAdd(&g_done, 1);
        if (old == NCTAS - 1) {
            double L = atomicAdd(&g_loss, 0.0);
            int    C = atomicAdd(&g_count, 0);
            double corr = (double)(FF * NN) * (double)fmaxf(margin, 0.f);
            if (nout > 0) gout[0] = (float)(L - corr);
            if (nout > 1) gout[1] = (float)C;
            g_loss = 0.0;
            g_count = 0;
            __threadfence();
            g_done = 0;
        }
    }
}

extern "C" void kernel_launch(void* const* d_in, const int* in_sizes, int n_in,
                              void* d_out, int out_size) {
    const float* out_matrix = (const float*)d_in[0];
    const float* label      = (const float*)d_in[1];
    const float* margin     = (const float*)d_in[2];
    float* out = (float*)d_out;

    cudaFuncSetAttribute(k_gemm, cudaFuncAttributeMaxDynamicSharedMemorySize, SM_TOTAL);

    dim3 gn(NN, 2);
    k_norm<<<gn, 256>>>(out_matrix);
    dim3 gm(NN / TM, FF);
    k_gemm<<<gm, THREADS, SM_TOTAL>>>(label, margin, out, out_size);
}

// round 9
// speedup vs baseline: 6.3354x; 1.0503x over previous
#include <cuda_runtime.h>
#include <cuda_fp16.h>
#include <math.h>
#include <stdint.h>

#define NN 2048
#define DD 128
#define FF 8
#define TM 64               // i-rows per CTA
#define TNJ 64              // j-cols per tile
#define NTILE (NN / TNJ)    // 32
#define THREADS 256
#define NCTAS ((NN / TM) * FF)   // 256
#define LP 68               // label smem pitch (floats): 272B, 16B-aligned rows

__device__ __half g_qh[FF * NN * DD];
__device__ __half g_dh[FF * NN * DD];
__device__ double g_loss;
__device__ int    g_count;
__device__ int    g_done;

__device__ __forceinline__ uint32_t smem_u32(const void* p) {
    uint32_t a;
    asm("{ .reg .u64 t; cvta.to.shared.u64 t, %1; cvt.u32.u64 %0, t; }" : "=r"(a) : "l"(p));
    return a;
}
__device__ __forceinline__ void cpa16(uint32_t dst, const void* src) {
    asm volatile("cp.async.cg.shared.global [%0], [%1], 16;" :: "r"(dst), "l"(src) : "memory");
}
#define CP_COMMIT() asm volatile("cp.async.commit_group;" ::: "memory")
#define CP_WAIT0()  asm volatile("cp.async.wait_group 0;" ::: "memory")

#define LDSM4(r, addr) \
    asm volatile("ldmatrix.sync.aligned.m8n8.x4.shared.b16 {%0,%1,%2,%3}, [%4];" \
                 : "=r"((r)[0]), "=r"((r)[1]), "=r"((r)[2]), "=r"((r)[3]) : "r"(addr))

__device__ __forceinline__ void mma_f16(float* c, const uint32_t* a, const uint32_t* b) {
    asm volatile(
        "mma.sync.aligned.m16n8k16.row.col.f32.f16.f16.f32 "
        "{%0,%1,%2,%3}, {%4,%5,%6,%7}, {%8,%9}, {%0,%1,%2,%3};"
        : "+f"(c[0]), "+f"(c[1]), "+f"(c[2]), "+f"(c[3])
        : "r"(a[0]), "r"(a[1]), "r"(a[2]), "r"(a[3]), "r"(b[0]), "r"(b[1]));
}

__device__ __forceinline__ uint32_t swz(int row, int chunk) {
    return (uint32_t)(row * 256 + ((chunk ^ (row & 7)) << 4));
}

// SMEM layout (per CTA, dynamic):
#define SM_AH   0
#define SM_B0   16384
#define SM_BSTR 16384
#define SM_L0   49152
#define SM_LSTR 17408       // 64 * 68 * 4
#define SM_DIAG 83968
#define SM_TOTAL (83968 + 512)

// ---------------- prep: normalize -> fp16 ----------------
__global__ void k_norm(const float* __restrict__ in0) {
    __shared__ float sd[DD * 9 + 9];
    int s = blockIdx.y, n = blockIdx.x;
    int tid = threadIdx.x;
    int f = tid >> 5, lane = tid & 31;
    const float4* base = (const float4*)(in0 + ((size_t)(s * NN + n)) * DD * FF);
    float4 v4 = base[tid];
    {
        int e = tid * 4;
        sd[((e + 0) >> 3) * 9 + ((e + 0) & 7)] = v4.x;
        sd[((e + 1) >> 3) * 9 + ((e + 1) & 7)] = v4.y;
        sd[((e + 2) >> 3) * 9 + ((e + 2) & 7)] = v4.z;
        sd[((e + 3) >> 3) * 9 + ((e + 3) & 7)] = v4.w;
    }
    __syncthreads();
    float v[4], ssq = 0.f;
#pragma unroll
    for (int k = 0; k < 4; k++) {
        v[k] = sd[(lane + 32 * k) * 9 + f];
        ssq += v[k] * v[k];
    }
#pragma unroll
    for (int off = 16; off; off >>= 1) ssq += __shfl_xor_sync(0xffffffffu, ssq, off);
    float rn = 1.0f / sqrtf(ssq);
    __half* oh = (s == 0 ? g_qh : g_dh) + ((size_t)(f * NN + n)) * DD;
#pragma unroll
    for (int k = 0; k < 4; k++)
        oh[lane + 32 * k] = __float2half_rn(v[k] * rn);
}

// B tile: ROWS x 128 fp16, swizzled
template <int ROWS>
__device__ __forceinline__ void load_tile_async(uint32_t smbase, const __half* src, int tid) {
#pragma unroll
    for (int it = 0; it < (ROWS * 16) / THREADS; it++) {
        int idx = tid + it * THREADS;
        int row = idx >> 4, c = idx & 15;
        cpa16(smbase + swz(row, c), src + row * DD + c * 8);
    }
}

// label tile: 64 rows x 64 floats -> smem pitch LP
__device__ __forceinline__ void load_lab_async(uint32_t smbase, const float* src, int tid) {
#pragma unroll
    for (int it = 0; it < 4; it++) {
        int idx = tid + it * THREADS;
        int row = idx >> 4, c = idx & 15;
        cpa16(smbase + (uint32_t)(row * (LP * 4) + c * 16), src + (size_t)row * NN + c * 4);
    }
}

// ---------------- main ----------------
__global__ void __launch_bounds__(THREADS, 2) k_gemm(const float* __restrict__ label,
                                                     const float* __restrict__ pmargin,
                                                     float* __restrict__ gout, int nout) {
    extern __shared__ __align__(1024) char sm[];
    const uint32_t smb = smem_u32(sm);
    const int tid = threadIdx.x;
    const int w = tid >> 5, lane = tid & 31;
    const int g = lane >> 2, t4 = lane & 3;
    const int rowgrp = w >> 2, colgrp = w & 3;     // 2 x 4 warp grid: 32 rows x 16 cols
    const int f = blockIdx.y;
    const int i0 = blockIdx.x * TM;
    const float margin = *pmargin;
    const size_t fb = (size_t)f * NN;
    float* sdS = (float*)(sm + SM_DIAG);
    float* sdL = sdS + TM;

    load_tile_async<TM>(smb + SM_AH, g_qh + (fb + i0) * DD, tid);
    load_tile_async<TNJ>(smb + SM_B0, g_dh + fb * DD, tid);
    load_lab_async(smb + SM_L0, label + (fb + i0) * NN, tid);
    CP_COMMIT();

    // fused diag: dS = qh . dh (fp32, matches MMA arithmetic)
    {
        const int d = lane * 4;
#pragma unroll 1
        for (int r8 = 0; r8 < 8; r8++) {
            int row = w * 8 + r8;
            const __half* qh = g_qh + (fb + i0 + row) * DD;
            const __half* dh = g_dh + (fb + i0 + row) * DD;
            float s = 0.f;
#pragma unroll
            for (int u = 0; u < 4; u++)
                s += __half2float(qh[d + u]) * __half2float(dh[d + u]);
#pragma unroll
            for (int off = 16; off; off >>= 1) s += __shfl_xor_sync(0xffffffffu, s, off);
            if (lane == 0) {
                sdS[row] = s;
                sdL[row] = label[(fb + i0 + row) * NN + (i0 + row)];
            }
        }
    }

    CP_WAIT0();
    __syncthreads();

    int rloc[4];
    float dS[4], dL[4];
#pragma unroll
    for (int mt = 0; mt < 2; mt++)
#pragma unroll
        for (int h = 0; h < 2; h++) {
            int k = mt * 2 + h;
            rloc[k] = rowgrp * 32 + mt * 16 + g + h * 8;
            dS[k] = sdS[rloc[k]];
            dL[k] = sdL[rloc[k]];
        }

    float smax[4], lmax[4];
    int sidx[4], lidx[4];
#pragma unroll
    for (int k = 0; k < 4; k++) {
        smax[k] = -INFINITY; lmax[k] = -INFINITY; sidx[k] = 0; lidx[k] = 0;
    }
    float loss = 0.f;

    const int arow0 = rowgrp * 32 + (lane & 15);
    const int ahalf = lane >> 4;
    // B x4: lanes 0-7 (nt0,kh0), 8-15 (nt0,kh1), 16-23 (nt1,kh0), 24-31 (nt1,kh1)
    const int brow = colgrp * 16 + ((lane >> 4) & 1) * 8 + (lane & 7);
    const int bhalf = (lane >> 3) & 1;
    const int jloc0 = colgrp * 16 + t4 * 2;    // local col of nt=0 element pair

#pragma unroll 1
    for (int t = 0; t < NTILE; t++) {
        if (t + 1 < NTILE) {
            uint32_t buf = (uint32_t)((t + 1) & 1);
            load_tile_async<TNJ>(smb + SM_B0 + buf * SM_BSTR,
                                 g_dh + (fb + (size_t)(t + 1) * TNJ) * DD, tid);
            load_lab_async(smb + SM_L0 + buf * SM_LSTR,
                           label + (fb + i0) * NN + (size_t)(t + 1) * TNJ, tid);
            CP_COMMIT();
        }
        const uint32_t bb = smb + SM_B0 + (uint32_t)(t & 1) * SM_BSTR;
        const float* ls = (const float*)(sm + SM_L0 + (t & 1) * SM_LSTR);
        const int j0 = t * TNJ;

        float acc[2][2][4];
#pragma unroll
        for (int mt = 0; mt < 2; mt++)
#pragma unroll
            for (int nt = 0; nt < 2; nt++)
#pragma unroll
                for (int u = 0; u < 4; u++) acc[mt][nt][u] = 0.f;

#pragma unroll
        for (int ks = 0; ks < 8; ks++) {
            uint32_t ah0[4], ah1[4], bfr[4];
            LDSM4(ah0, smb + SM_AH + swz(arow0,      2 * ks + ahalf));
            LDSM4(ah1, smb + SM_AH + swz(arow0 + 16, 2 * ks + ahalf));
            LDSM4(bfr, bb + swz(brow, 2 * ks + bhalf));
            mma_f16(acc[0][0], ah0, bfr + 0);
            mma_f16(acc[1][0], ah1, bfr + 0);
            mma_f16(acc[0][1], ah0, bfr + 2);
            mma_f16(acc[1][1], ah1, bfr + 2);
        }

        // epilogue: labels from smem (diag contributes exactly `margin`; fixed at finalize)
#pragma unroll
        for (int mt = 0; mt < 2; mt++)
#pragma unroll
            for (int nt = 0; nt < 2; nt++) {
                const int jl = jloc0 + nt * 8;
                const int j = j0 + jl;
#pragma unroll
                for (int h = 0; h < 2; h++) {
                    const int k = mt * 2 + h;
                    float2 l2 = *(const float2*)&ls[rloc[k] * LP + jl];
                    float s0 = acc[mt][nt][2 * h + 0];
                    float s1 = acc[mt][nt][2 * h + 1];
                    if (s0 > smax[k]) { smax[k] = s0; sidx[k] = j; }
                    if (s1 > smax[k]) { smax[k] = s1; sidx[k] = j + 1; }
                    if (l2.x > lmax[k]) { lmax[k] = l2.x; lidx[k] = j; }
                    if (l2.y > lmax[k]) { lmax[k] = l2.y; lidx[k] = j + 1; }
                    loss += fmaxf(margin - (dS[k] - s0) * (dL[k] - l2.x), 0.f);
                    loss += fmaxf(margin - (dS[k] - s1) * (dL[k] - l2.y), 0.f);
                }
            }

        if (t + 1 < NTILE) {
            CP_WAIT0();
            __syncthreads();
        }
    }

    // ---- loss ----
#pragma unroll
    for (int off = 16; off; off >>= 1) loss += __shfl_xor_sync(0xffffffffu, loss, off);
    if (lane == 0) atomicAdd(&g_loss, (double)loss);

    // ---- argmax: quad reduce then cross-colgrp merge ----
#pragma unroll
    for (int k = 0; k < 4; k++) {
#pragma unroll
        for (int o = 1; o < 4; o <<= 1) {
            float v; int ix;
            v = __shfl_xor_sync(0xffffffffu, smax[k], o); ix = __shfl_xor_sync(0xffffffffu, sidx[k], o);
            if (v > smax[k] || (v == smax[k] && ix < sidx[k])) { smax[k] = v; sidx[k] = ix; }
            v = __shfl_xor_sync(0xffffffffu, lmax[k], o); ix = __shfl_xor_sync(0xffffffffu, lidx[k], o);
            if (v > lmax[k] || (v == lmax[k] && ix < lidx[k])) { lmax[k] = v; lidx[k] = ix; }
        }
    }

    __syncthreads();                    // A smem dead -> reuse
    float* ms = (float*)sm;
    int*   mi = (int*)(sm + 1024);
    float* Ls = (float*)(sm + 2048);
    int*   Li = (int*)(sm + 3072);
    if (t4 == 0) {
#pragma unroll
        for (int k = 0; k < 4; k++) {
            ms[colgrp * TM + rloc[k]] = smax[k];
            mi[colgrp * TM + rloc[k]] = sidx[k];
            Ls[colgrp * TM + rloc[k]] = lmax[k];
            Li[colgrp * TM + rloc[k]] = lidx[k];
        }
    }
    __syncthreads();
    int match = 0;
    if (tid < TM) {
        float bs = -INFINITY, bl = -INFINITY;
        int bsi = 0, bli = 0;
#pragma unroll
        for (int c = 0; c < 4; c++) {
            float v = ms[c * TM + tid]; int ix = mi[c * TM + tid];
            if (v > bs || (v == bs && ix < bsi)) { bs = v; bsi = ix; }
            float u = Ls[c * TM + tid]; int jx = Li[c * TM + tid];
            if (u > bl || (u == bl && jx < bli)) { bl = u; bli = jx; }
        }
        match = (bsi == bli);
    }
    match = __reduce_add_sync(0xffffffffu, match);
    if (lane == 0 && w < (TM / 32) && match) atomicAdd(&g_count, match);

    // ---- fused finalize ----
    __syncthreads();
    if (tid == 0) {
        __threadfence();
        int old = atomicAdd(&g_done, 1);
        if (old == NCTAS - 1) {
            double L = atomicAdd(&g_loss, 0.0);
            int    C = atomicAdd(&g_count, 0);
            double corr = (double)(FF * NN) * (double)fmaxf(margin, 0.f);
            if (nout > 0) gout[0] = (float)(L - corr);
            if (nout > 1) gout[1] = (float)C;
            g_loss = 0.0;
            g_count = 0;
            __threadfence();
            g_done = 0;
        }
    }
}

extern "C" void kernel_launch(void* const* d_in, const int* in_sizes, int n_in,
                              void* d_out, int out_size) {
    const float* out_matrix = (const float*)d_in[0];
    const float* label      = (const float*)d_in[1];
    const float* margin     = (const float*)d_in[2];
    float* out = (float*)d_out;

    cudaFuncSetAttribute(k_gemm, cudaFuncAttributeMaxDynamicSharedMemorySize, SM_TOTAL);

    dim3 gn(NN, 2);
    k_norm<<<gn, 256>>>(out_matrix);
    dim3 gm(NN / TM, FF);
    k_gemm<<<gm, THREADS, SM_TOTAL>>>(label, margin, out, out_size);
}